// round 16
// baseline (speedup 1.0000x reference)
#include <cuda_runtime.h>
#include <cuda_fp16.h>
#include <math.h>
#include <stdint.h>

// ---------------- problem constants ----------------
#define MWIN   8192
#define KTOK   32
#define TOK    33          // K + G
#define CCH    256
#define HEADS  8
#define HDIM   32
#define NPTS   (MWIN * KTOK)        // 262144
#define ROWS   (MWIN * TOK)         // 270336
#define HID    1024
#define NEIGH  27
#define POS_BND 25
#define RPE_NUM 51
#define C3     768

// ---------------- scratch ----------------
__device__ float  g_xbuf [(size_t)ROWS * CCH];
__device__ __half g_hbuf16[(size_t)ROWS * CCH];
__device__ __half g_big16 [(size_t)ROWS * HID];
__device__ __half g_wT16  [768*256 + 256*256 + 1024*256 + 256*1024];
__device__ __half g_data16[(size_t)NPTS * CCH];

// ---------------- PTX helpers ----------------
__device__ __forceinline__ uint32_t smem_u32(const void* p) {
    uint32_t a;
    asm("{ .reg .u64 t; cvta.to.shared.u64 t, %1; cvt.u32.u64 %0, t; }" : "=r"(a) : "l"(p));
    return a;
}
#define CP_ASYNC16(dst_u32, src_ptr) \
    asm volatile("cp.async.cg.shared.global [%0], [%1], 16;\n" :: "r"(dst_u32), "l"(src_ptr))
#define CP_COMMIT() asm volatile("cp.async.commit_group;\n")
#define CP_WAIT(n)  asm volatile("cp.async.wait_group %0;\n" :: "n"(n))

#define LDSM_X4(r0,r1,r2,r3,a) \
    asm volatile("ldmatrix.sync.aligned.m8n8.x4.shared.b16 {%0,%1,%2,%3}, [%4];" \
        : "=r"(r0),"=r"(r1),"=r"(r2),"=r"(r3) : "r"(a))

#define HMMA16816(d, a, b) \
    asm volatile("mma.sync.aligned.m16n8k16.row.col.f32.f16.f16.f32 " \
        "{%0,%1,%2,%3},{%4,%5,%6,%7},{%8,%9},{%0,%1,%2,%3};" \
        : "+f"((d)[0]),"+f"((d)[1]),"+f"((d)[2]),"+f"((d)[3]) \
        : "r"((a)[0]),"r"((a)[1]),"r"((a)[2]),"r"((a)[3]),"r"((b)[0]),"r"((b)[1]))

#define HMMA16816H(d, a, b) \
    asm volatile("mma.sync.aligned.m16n8k16.row.col.f16.f16.f16.f16 " \
        "{%0,%1},{%2,%3,%4,%5},{%6,%7},{%0,%1};" \
        : "+r"((d)[0]), "+r"((d)[1]) \
        : "r"((a)[0]),"r"((a)[1]),"r"((a)[2]),"r"((a)[3]),"r"((b)[0]),"r"((b)[1]))

// ---------------- merged weight transpose ----------------
__global__ void __launch_bounds__(256) wt_all(
    const float* __restrict__ w0, const float* __restrict__ w1,
    const float* __restrict__ w2, const float* __restrict__ w3,
    __half* __restrict__ o0, __half* __restrict__ o1,
    __half* __restrict__ o2, __half* __restrict__ o3)
{
    int z = blockIdx.z;
    const float* in; __half* out; int K, N;
    if      (z == 0) { in = w0; out = o0; K = 256;  N = 768;  }
    else if (z == 1) { in = w1; out = o1; K = 256;  N = 256;  }
    else if (z == 2) { in = w2; out = o2; K = 256;  N = 1024; }
    else             { in = w3; out = o3; K = 1024; N = 256;  }
    int bx = blockIdx.x * 32, by = blockIdx.y * 32;
    if (bx >= N || by >= K) return;

    __shared__ float tile[32][33];
    int x = threadIdx.x & 31, y = threadIdx.x >> 5;
    #pragma unroll
    for (int i = 0; i < 32; i += 8)
        tile[y + i][x] = in[(size_t)(by + y + i) * N + bx + x];
    __syncthreads();
    #pragma unroll
    for (int i = 0; i < 32; i += 8)
        out[(size_t)(bx + y + i) * K + by + x] = __float2half(tile[x][y + i]);
}

// ---------------- data -> fp16 mirror ----------------
__global__ void __launch_bounds__(256) cvt_data_kernel(const float* __restrict__ data)
{
    size_t i = ((size_t)blockIdx.x * 256 + threadIdx.x) * 4;
    float4 f = *(const float4*)(data + i);
    __half2* d = (__half2*)(g_data16 + i);
    d[0] = __floats2half2_rn(f.x, f.y);
    d[1] = __floats2half2_rn(f.z, f.w);
}

// ---------------- CPE gather + residual + fused LN1 ----------------
__global__ void __launch_bounds__(128) cpe_ln_kernel(
    const float* __restrict__ data, const float* __restrict__ rt,
    const int* __restrict__ neighbors, const float* __restrict__ cpe_w,
    const float* __restrict__ cpe_scale, const float* __restrict__ cpe_bias,
    const float* __restrict__ gam, const float* __restrict__ bet)
{
    __shared__ int nb[NEIGH];
    __shared__ float red[8];
    int bid = blockIdx.x;
    int tid = threadIdx.x;
    int c = tid * 2;
    float2 v;
    size_t row;

    if (bid >= NPTS) {
        int m = bid - NPTS;
        row = (size_t)m * TOK;
        v = *(const float2*)(rt + (size_t)m * CCH + c);
    } else {
        if (tid < NEIGH) nb[tid] = neighbors[(size_t)bid * NEIGH + tid];
        __syncthreads();
        float ax = 0.f, ay = 0.f;
        #pragma unroll
        for (int j = 0; j < NEIGH; j++) {
            __half2 h = *(const __half2*)(g_data16 + (size_t)nb[j] * CCH + c);
            float2 f = __half22float2(h);
            float2 w = *(const float2*)(cpe_w + j * CCH + c);
            ax += f.x * w.x; ay += f.y * w.y;
        }
        float2 d0 = *(const float2*)(data + (size_t)bid * CCH + c);
        float2 sc = *(const float2*)(cpe_scale + c);
        float2 bi = *(const float2*)(cpe_bias + c);
        v = make_float2(d0.x + ax * sc.x + bi.x, d0.y + ay * sc.y + bi.y);
        int m = bid >> 5, k = bid & 31;
        row = (size_t)m * TOK + 1 + k;
    }
    *(float2*)(g_xbuf + row * CCH + c) = v;

    float s1 = v.x + v.y;
    float s2 = v.x * v.x + v.y * v.y;
    #pragma unroll
    for (int o = 16; o; o >>= 1) {
        s1 += __shfl_xor_sync(0xffffffffu, s1, o);
        s2 += __shfl_xor_sync(0xffffffffu, s2, o);
    }
    int warp = tid >> 5, lane = tid & 31;
    if (lane == 0) { red[warp] = s1; red[4 + warp] = s2; }
    __syncthreads();
    s1 = red[0] + red[1] + red[2] + red[3];
    s2 = red[4] + red[5] + red[6] + red[7];
    float mean = s1 * (1.f / 256.f);
    float var = s2 * (1.f / 256.f) - mean * mean;
    float rstd = rsqrtf(var + 1e-5f);
    float2 gm = *(const float2*)(gam + c);
    float2 bt = *(const float2*)(bet + c);
    *(__half2*)(g_hbuf16 + row * CCH + c) = __floats2half2_rn(
        (v.x - mean) * rstd * gm.x + bt.x, (v.y - mean) * rstd * gm.y + bt.y);
}

#define A_TILE1  10240            // 128 rows * 80 bytes
#define B_TILE1  20480            // 256 rows * 80 bytes

// ===== hg256h: fp16-acc GEMM, CTA 128x256, warp tile 64x64, 2 CTAs/SM (qkv) =====
#define GEMM256H_SMEM (3 * (A_TILE1 + B_TILE1))   // 92160

template<int MODE>
__global__ void __launch_bounds__(256, 2) hg256h(
    const __half* __restrict__ A, const __half* __restrict__ Bt,
    const float* __restrict__ bias, __half* __restrict__ Cout,
    int Kdim, int Ndim)
{
    extern __shared__ char smraw[];
    uint32_t base = smem_u32(smraw);

    int tid = threadIdx.x;
    int warp = tid >> 5, lane = tid & 31;
    int wm = (warp >> 2) * 64;
    int wn = (warp & 3) * 64;
    int la = lane & 7, grp = lane >> 3;
    int g = lane >> 2, t = lane & 3;

    size_t rowBase = (size_t)blockIdx.y * 128;
    int colBase = blockIdx.x * 256;

    const __half* Ag = A  + rowBase * Kdim;
    const __half* Bg = Bt + (size_t)colBase * Kdim;

    int aRow = la + (grp & 1) * 8;
    int aKof = (grp >> 1) * 8;
    int bRow = la + (grp >> 1) * 8;
    int bKof = (grp & 1) * 8;

    uint32_t accH[4][8][2];
    #pragma unroll
    for (int mt = 0; mt < 4; mt++)
        #pragma unroll
        for (int nt = 0; nt < 8; nt++) { accH[mt][nt][0] = 0u; accH[mt][nt][1] = 0u; }

    auto loadStage = [&](int s, int k0) {
        #pragma unroll
        for (int i = 0; i < 2; i++) {
            int idx = i * 256 + tid;
            int row = idx >> 2, c = idx & 3;
            CP_ASYNC16(base + s * A_TILE1 + row * 80 + c * 16,
                       Ag + (size_t)row * Kdim + k0 + c * 8);
        }
        #pragma unroll
        for (int i = 0; i < 4; i++) {
            int idx = i * 256 + tid;
            int row = idx >> 2, c = idx & 3;
            CP_ASYNC16(base + 3 * A_TILE1 + s * B_TILE1 + row * 80 + c * 16,
                       Bg + (size_t)row * Kdim + k0 + c * 8);
        }
    };

    int KT = Kdim >> 5;
    loadStage(0, 0);  CP_COMMIT();
    loadStage(1, 32); CP_COMMIT();

    for (int kt = 0; kt < KT; kt++) {
        if (kt + 1 < KT) CP_WAIT(1); else CP_WAIT(0);
        __syncthreads();
        if (kt + 2 < KT) { loadStage((kt + 2) % 3, (kt + 2) << 5); CP_COMMIT(); }

        int buf = kt % 3;
        uint32_t aBase = base + buf * A_TILE1;
        uint32_t bBase = base + 3 * A_TILE1 + buf * B_TILE1;

        #pragma unroll
        for (int kk = 0; kk < 2; kk++) {
            int kb = kk * 16;
            uint32_t af[4][4], bf[8][2];
            #pragma unroll
            for (int mt = 0; mt < 4; mt++) {
                uint32_t ad = aBase + (uint32_t)(wm + mt * 16 + aRow) * 80
                            + (uint32_t)(kb + aKof) * 2;
                LDSM_X4(af[mt][0], af[mt][1], af[mt][2], af[mt][3], ad);
            }
            #pragma unroll
            for (int np = 0; np < 4; np++) {
                uint32_t bd = bBase + (uint32_t)(wn + np * 16 + bRow) * 80
                            + (uint32_t)(kb + bKof) * 2;
                LDSM_X4(bf[2*np][0], bf[2*np][1], bf[2*np+1][0], bf[2*np+1][1], bd);
            }
            #pragma unroll
            for (int mt = 0; mt < 4; mt++)
                #pragma unroll
                for (int nt = 0; nt < 8; nt++)
                    HMMA16816H(accH[mt][nt], af[mt], bf[nt]);
        }
    }

    #pragma unroll
    for (int mt = 0; mt < 4; mt++) {
        #pragma unroll
        for (int nt = 0; nt < 8; nt++) {
            int col = colBase + wn + nt * 8 + 2 * t;
            float b0 = bias[col], b1 = bias[col + 1];
            #pragma unroll
            for (int hf = 0; hf < 2; hf++) {
                size_t row = rowBase + wm + mt * 16 + g + hf * 8;
                float2 f = __half22float2(*(__half2*)&accH[mt][nt][hf]);
                float v0 = f.x + b0;
                float v1 = f.y + b1;
                if (MODE == 2) {
                    v0 = 0.5f * v0 * (1.0f + erff(v0 * 0.70710678118654752f));
                    v1 = 0.5f * v1 * (1.0f + erff(v1 * 0.70710678118654752f));
                }
                *(__half2*)&Cout[row * Ndim + col] = __floats2half2_rn(v0, v1);
            }
        }
    }
}

// ===== hg128h: fp16-acc GEMM, CTA 128x128, 3 CTAs/SM (mlp1) =====
#define GEMMH_SMEM (6 * A_TILE1)  // 61440

template<int MODE>
__global__ void __launch_bounds__(256, 3) hg128h(
    const __half* __restrict__ A, const __half* __restrict__ Bt,
    const float* __restrict__ bias, __half* __restrict__ Cout,
    int Kdim, int Ndim)
{
    extern __shared__ char smraw[];
    uint32_t base = smem_u32(smraw);

    int tid = threadIdx.x;
    int warp = tid >> 5, lane = tid & 31;
    int wm = (warp >> 2) * 64;
    int wn = (warp & 3) * 32;
    int la = lane & 7, grp = lane >> 3;
    int g = lane >> 2, t = lane & 3;

    size_t rowBase = (size_t)blockIdx.y * 128;
    int colBase = blockIdx.x * 128;

    const __half* Ag = A  + rowBase * Kdim;
    const __half* Bg = Bt + (size_t)colBase * Kdim;

    int aRow = la + (grp & 1) * 8;
    int aKof = (grp >> 1) * 8;
    int bRow = la + (grp >> 1) * 8;
    int bKof = (grp & 1) * 8;

    uint32_t accH[4][4][2];
    #pragma unroll
    for (int mt = 0; mt < 4; mt++)
        #pragma unroll
        for (int nt = 0; nt < 4; nt++) { accH[mt][nt][0] = 0u; accH[mt][nt][1] = 0u; }

    auto loadStage = [&](int s, int k0) {
        #pragma unroll
        for (int i = 0; i < 2; i++) {
            int idx = i * 256 + tid;
            int row = idx >> 2, c = idx & 3;
            CP_ASYNC16(base + s * A_TILE1 + row * 80 + c * 16,
                       Ag + (size_t)row * Kdim + k0 + c * 8);
            CP_ASYNC16(base + (3 + s) * A_TILE1 + row * 80 + c * 16,
                       Bg + (size_t)row * Kdim + k0 + c * 8);
        }
    };

    int KT = Kdim >> 5;
    loadStage(0, 0);  CP_COMMIT();
    loadStage(1, 32); CP_COMMIT();

    for (int kt = 0; kt < KT; kt++) {
        if (kt + 1 < KT) CP_WAIT(1); else CP_WAIT(0);
        __syncthreads();
        if (kt + 2 < KT) { loadStage((kt + 2) % 3, (kt + 2) << 5); CP_COMMIT(); }

        int buf = kt % 3;
        uint32_t aBase = base + buf * A_TILE1;
        uint32_t bBase = base + (3 + buf) * A_TILE1;

        #pragma unroll
        for (int kk = 0; kk < 2; kk++) {
            int kb = kk * 16;
            uint32_t af[4][4], bf[4][2];
            #pragma unroll
            for (int mt = 0; mt < 4; mt++) {
                uint32_t ad = aBase + (uint32_t)(wm + mt * 16 + aRow) * 80
                            + (uint32_t)(kb + aKof) * 2;
                LDSM_X4(af[mt][0], af[mt][1], af[mt][2], af[mt][3], ad);
            }
            #pragma unroll
            for (int np = 0; np < 2; np++) {
                uint32_t bd = bBase + (uint32_t)(wn + np * 16 + bRow) * 80
                            + (uint32_t)(kb + bKof) * 2;
                LDSM_X4(bf[2*np][0], bf[2*np][1], bf[2*np+1][0], bf[2*np+1][1], bd);
            }
            #pragma unroll
            for (int mt = 0; mt < 4; mt++)
                #pragma unroll
                for (int nt = 0; nt < 4; nt++)
                    HMMA16816H(accH[mt][nt], af[mt], bf[nt]);
        }
        __syncthreads();
    }

    #pragma unroll
    for (int mt = 0; mt < 4; mt++) {
        #pragma unroll
        for (int nt = 0; nt < 4; nt++) {
            int col = colBase + wn + nt * 8 + 2 * t;
            float b0 = bias[col], b1 = bias[col + 1];
            #pragma unroll
            for (int hf = 0; hf < 2; hf++) {
                size_t row = rowBase + wm + mt * 16 + g + hf * 8;
                float2 f = __half22float2(*(__half2*)&accH[mt][nt][hf]);
                float v0 = f.x + b0;
                float v1 = f.y + b1;
                if (MODE == 2) {
                    v0 = 0.5f * v0 * (1.0f + erff(v0 * 0.70710678118654752f));
                    v1 = 0.5f * v1 * (1.0f + erff(v1 * 0.70710678118654752f));
                }
                *(__half2*)&Cout[row * Ndim + col] = __floats2half2_rn(v0, v1);
            }
        }
    }
}

// ===== hg128: fp32-acc GEMM (mlp2/output), CTA 128x128, 2 CTAs/SM, 5-stage =====
#define NSTG     5
#define GEMM1_SMEM (2 * NSTG * A_TILE1)  // 102400

template<int MODE, typename OutT>
__global__ void __launch_bounds__(256, 2) hg128(
    const __half* __restrict__ A, const __half* __restrict__ Bt,
    const float* __restrict__ bias, OutT* __restrict__ Cout,
    const float* __restrict__ res, int Kdim, int Ndim)
{
    extern __shared__ char smraw[];
    uint32_t base = smem_u32(smraw);

    int tid = threadIdx.x;
    int warp = tid >> 5, lane = tid & 31;
    int wm = (warp >> 2) * 64;
    int wn = (warp & 3) * 32;
    int la = lane & 7, grp = lane >> 3;
    int g = lane >> 2, t = lane & 3;

    size_t rowBase = (size_t)blockIdx.y * 128;
    int colBase = blockIdx.x * 128;

    const __half* Ag = A  + rowBase * Kdim;
    const __half* Bg = Bt + (size_t)colBase * Kdim;

    int aRow = la + (grp & 1) * 8;
    int aKof = (grp >> 1) * 8;
    int bRow = la + (grp >> 1) * 8;
    int bKof = (grp & 1) * 8;

    float acc[4][4][4];
    #pragma unroll
    for (int mt = 0; mt < 4; mt++)
        #pragma unroll
        for (int nt = 0; nt < 4; nt++)
            #pragma unroll
            for (int i = 0; i < 4; i++) acc[mt][nt][i] = 0.f;

    auto loadStage = [&](int s, int k0) {
        #pragma unroll
        for (int i = 0; i < 2; i++) {
            int idx = i * 256 + tid;
            int row = idx >> 2, c = idx & 3;
            CP_ASYNC16(base + s * A_TILE1 + row * 80 + c * 16,
                       Ag + (size_t)row * Kdim + k0 + c * 8);
            CP_ASYNC16(base + (NSTG + s) * A_TILE1 + row * 80 + c * 16,
                       Bg + (size_t)row * Kdim + k0 + c * 8);
        }
    };

    auto computeStage = [&](int buf) {
        uint32_t aBase = base + buf * A_TILE1;
        uint32_t bBase = base + (NSTG + buf) * A_TILE1;
        #pragma unroll
        for (int kk = 0; kk < 2; kk++) {
            int kb = kk * 16;
            uint32_t af[4][4], bf[4][2];
            #pragma unroll
            for (int mt = 0; mt < 4; mt++) {
                uint32_t ad = aBase + (uint32_t)(wm + mt * 16 + aRow) * 80
                            + (uint32_t)(kb + aKof) * 2;
                LDSM_X4(af[mt][0], af[mt][1], af[mt][2], af[mt][3], ad);
            }
            #pragma unroll
            for (int np = 0; np < 2; np++) {
                uint32_t bd = bBase + (uint32_t)(wn + np * 16 + bRow) * 80
                            + (uint32_t)(kb + bKof) * 2;
                LDSM_X4(bf[2*np][0], bf[2*np][1], bf[2*np+1][0], bf[2*np+1][1], bd);
            }
            #pragma unroll
            for (int mt = 0; mt < 4; mt++)
                #pragma unroll
                for (int nt = 0; nt < 4; nt++)
                    HMMA16816(acc[mt][nt], af[mt], bf[nt]);
        }
    };

    int KT = Kdim >> 5;
    loadStage(0, 0);   CP_COMMIT();
    loadStage(1, 32);  CP_COMMIT();
    loadStage(2, 64);  CP_COMMIT();

    for (int kt = 0; kt < KT; kt += 2) {
        if (kt + 2 < KT) CP_WAIT(1); else CP_WAIT(0);
        __syncthreads();
        if (kt + 3 < KT) { loadStage((kt + 3) % NSTG, (kt + 3) << 5); CP_COMMIT(); }
        if (kt + 4 < KT) { loadStage((kt + 4) % NSTG, (kt + 4) << 5); CP_COMMIT(); }
        computeStage(kt % NSTG);
        computeStage((kt + 1) % NSTG);
    }

    #pragma unroll
    for (int mt = 0; mt < 4; mt++) {
        #pragma unroll
        for (int nt = 0; nt < 4; nt++) {
            int col = colBase + wn + nt * 8 + 2 * t;
            float b0 = bias[col], b1 = bias[col + 1];
            #pragma unroll
            for (int hf = 0; hf < 2; hf++) {
                size_t row = rowBase + wm + mt * 16 + g + hf * 8;
                float v0 = acc[mt][nt][hf * 2 + 0] + b0;
                float v1 = acc[mt][nt][hf * 2 + 1] + b1;
                const float2 r2 = *(const float2*)&res[row * CCH + col];
                size_t m = row / TOK;
                int tt = (int)(row - m * TOK);
                float* dst = (tt == 0)
                    ? ((float*)Cout + (size_t)NPTS * CCH + m * CCH + col)
                    : ((float*)Cout + (m * KTOK + (size_t)(tt - 1)) * CCH + col);
                *(float2*)dst = make_float2(v0 + r2.x, v1 + r2.y);
            }
        }
    }
}

// ===== hg256h_ln: proj + residual + fused LN2; fp16 acc, 2 CTAs/SM =====
// grid.x must be 1 (CTA holds complete 256-col rows). Cout = xbuf (fp32), hout = LN'd fp16.
__global__ void __launch_bounds__(256, 2) hg256h_ln(
    const __half* __restrict__ A, const __half* __restrict__ Bt,
    const float* __restrict__ bias, float* __restrict__ Cout,
    const float* __restrict__ res, int Kdim, int Ndim,
    const float* __restrict__ gam, const float* __restrict__ bet,
    __half* __restrict__ hout)
{
    extern __shared__ char smraw[];
    uint32_t base = smem_u32(smraw);
    float* lnsum = (float*)smraw;          // reused after mainloop
    float* lnsq  = (float*)smraw + 128;

    int tid = threadIdx.x;
    int warp = tid >> 5, lane = tid & 31;
    int wm = (warp >> 2) * 64;
    int wn = (warp & 3) * 64;
    int la = lane & 7, grp = lane >> 3;
    int g = lane >> 2, t = lane & 3;

    size_t rowBase = (size_t)blockIdx.y * 128;

    const __half* Ag = A + rowBase * Kdim;
    const __half* Bg = Bt;

    int aRow = la + (grp & 1) * 8;
    int aKof = (grp >> 1) * 8;
    int bRow = la + (grp >> 1) * 8;
    int bKof = (grp & 1) * 8;

    uint32_t accH[4][8][2];
    #pragma unroll
    for (int mt = 0; mt < 4; mt++)
        #pragma unroll
        for (int nt = 0; nt < 8; nt++) { accH[mt][nt][0] = 0u; accH[mt][nt][1] = 0u; }

    auto loadStage = [&](int s, int k0) {
        #pragma unroll
        for (int i = 0; i < 2; i++) {
            int idx = i * 256 + tid;
            int row = idx >> 2, c = idx & 3;
            CP_ASYNC16(base + s * A_TILE1 + row * 80 + c * 16,
                       Ag + (size_t)row * Kdim + k0 + c * 8);
        }
        #pragma unroll
        for (int i = 0; i < 4; i++) {
            int idx = i * 256 + tid;
            int row = idx >> 2, c = idx & 3;
            CP_ASYNC16(base + 3 * A_TILE1 + s * B_TILE1 + row * 80 + c * 16,
                       Bg + (size_t)row * Kdim + k0 + c * 8);
        }
    };

    int KT = Kdim >> 5;   // 8
    loadStage(0, 0);  CP_COMMIT();
    loadStage(1, 32); CP_COMMIT();

    for (int kt = 0; kt < KT; kt++) {
        if (kt + 1 < KT) CP_WAIT(1); else CP_WAIT(0);
        __syncthreads();
        if (kt + 2 < KT) { loadStage((kt + 2) % 3, (kt + 2) << 5); CP_COMMIT(); }

        int buf = kt % 3;
        uint32_t aBase = base + buf * A_TILE1;
        uint32_t bBase = base + 3 * A_TILE1 + buf * B_TILE1;

        #pragma unroll
        for (int kk = 0; kk < 2; kk++) {
            int kb = kk * 16;
            uint32_t af[4][4], bf[8][2];
            #pragma unroll
            for (int mt = 0; mt < 4; mt++) {
                uint32_t ad = aBase + (uint32_t)(wm + mt * 16 + aRow) * 80
                            + (uint32_t)(kb + aKof) * 2;
                LDSM_X4(af[mt][0], af[mt][1], af[mt][2], af[mt][3], ad);
            }
            #pragma unroll
            for (int np = 0; np < 4; np++) {
                uint32_t bd = bBase + (uint32_t)(wn + np * 16 + bRow) * 80
                            + (uint32_t)(kb + bKof) * 2;
                LDSM_X4(bf[2*np][0], bf[2*np][1], bf[2*np+1][0], bf[2*np+1][1], bd);
            }
            #pragma unroll
            for (int mt = 0; mt < 4; mt++)
                #pragma unroll
                for (int nt = 0; nt < 8; nt++)
                    HMMA16816H(accH[mt][nt], af[mt], bf[nt]);
        }
    }

    __syncthreads();
    if (tid < 128) lnsum[tid] = 0.f;
    else lnsq[tid - 128] = 0.f;
    __syncthreads();

    // pass 1: v = acc + bias + res; write xbuf; accumulate LN stats
    #pragma unroll
    for (int mt = 0; mt < 4; mt++) {
        #pragma unroll
        for (int hf = 0; hf < 2; hf++) {
            int rloc = wm + mt * 16 + g + hf * 8;
            size_t row = rowBase + rloc;
            float s1 = 0.f, s2 = 0.f;
            #pragma unroll
            for (int nt = 0; nt < 8; nt++) {
                int col = wn + nt * 8 + 2 * t;
                float2 f = __half22float2(*(__half2*)&accH[mt][nt][hf]);
                const float2 r2 = *(const float2*)&res[row * Ndim + col];
                float v0 = f.x + bias[col]     + r2.x;
                float v1 = f.y + bias[col + 1] + r2.y;
                *(float2*)&Cout[row * Ndim + col] = make_float2(v0, v1);
                s1 += v0 + v1;
                s2 += v0 * v0 + v1 * v1;
            }
            s1 += __shfl_xor_sync(0xffffffffu, s1, 1);
            s1 += __shfl_xor_sync(0xffffffffu, s1, 2);
            s2 += __shfl_xor_sync(0xffffffffu, s2, 1);
            s2 += __shfl_xor_sync(0xffffffffu, s2, 2);
            if (t == 0) {
                atomicAdd(&lnsum[rloc], s1);
                atomicAdd(&lnsq[rloc],  s2);
            }
        }
    }
    __syncthreads();

    // pass 2: re-read own values from Cout (L2-hot), apply LN, write hout
    #pragma unroll
    for (int mt = 0; mt < 4; mt++) {
        #pragma unroll
        for (int hf = 0; hf < 2; hf++) {
            int rloc = wm + mt * 16 + g + hf * 8;
            size_t row = rowBase + rloc;
            float mean = lnsum[rloc] * (1.f / 256.f);
            float var  = lnsq[rloc] * (1.f / 256.f) - mean * mean;
            float rstd = rsqrtf(var + 1e-5f);
            #pragma unroll
            for (int nt = 0; nt < 8; nt++) {
                int col = wn + nt * 8 + 2 * t;
                const float2 v2 = *(const float2*)&Cout[row * Ndim + col];
                float o0 = (v2.x - mean) * rstd * gam[col]     + bet[col];
                float o1 = (v2.y - mean) * rstd * gam[col + 1] + bet[col + 1];
                *(__half2*)&hout[row * CCH + col] = __floats2half2_rn(o0, o1);
            }
        }
    }
}

// ---------------- fused per-window attention (R7 exact) ----------------
#define ATTN_THREADS 512
#define SQH_H  (TOK * C3)
#define KT2_E  ((CCH / 2) * TOK)
#define SC_F   (HEADS * TOK * TOK)
#define TAB_F  (3 * RPE_NUM * HEADS)
#define ATTN_SMEM (SQH_H * 2 + KT2_E * 4 + SC_F * 4 + TAB_F * 4)

__global__ void __launch_bounds__(ATTN_THREADS) attn_kernel(
    const __half* __restrict__ qkv, const int* __restrict__ rel_pos,
    const float* __restrict__ mask, const float* __restrict__ rpe_table,
    __half* __restrict__ outbuf)
{
    extern __shared__ char smc[];
    __half*  sqh    = (__half*)smc;
    __half2* ktb2   = (__half2*)(smc + SQH_H * 2);
    float*   sscore = (float*)(smc + SQH_H * 2 + KT2_E * 4);
    float*   stab   = sscore + SC_F;

    int m = blockIdx.x, tid = threadIdx.x;
    const __half2* src = (const __half2*)(qkv + (size_t)m * TOK * C3);
    __half2* dsq = (__half2*)sqh;
    for (int i = tid; i < SQH_H / 2; i += ATTN_THREADS) dsq[i] = src[i];
    for (int i = tid; i < TAB_F; i += ATTN_THREADS) stab[i] = rpe_table[i];
    __syncthreads();

    for (int idx = tid; idx < KT2_E; idx += ATTN_THREADS) {
        int c2 = idx & 127, j = idx >> 7;
        ktb2[c2 * TOK + j] = *(const __half2*)(sqh + j * C3 + CCH + c2 * 2);
    }
    __syncthreads();

    const float scale = 0.17677669529663687f;

    for (int idx = tid; idx < SC_F; idx += ATTN_THREADS) {
        int j = idx % TOK;
        int ih = idx / TOK;
        int i = ih % TOK;
        int h = ih / TOK;
        const __half2* qp = (const __half2*)(sqh + i * C3 + h * HDIM);
        const __half2* kp = ktb2 + (h * 16) * TOK + j;
        float s = 0.f;
        #pragma unroll
        for (int d2 = 0; d2 < 16; d2++) {
            float2 q2 = __half22float2(qp[d2]);
            float2 k2 = __half22float2(kp[d2 * TOK]);
            s += q2.x * k2.x + q2.y * k2.y;
        }
        s *= scale;
        if (i > 0 && j > 0) {
            const int* rp = rel_pos + (((size_t)m * KTOK + (i - 1)) * KTOK + (j - 1)) * 3;
            #pragma unroll
            for (int dd = 0; dd < 3; dd++) {
                int r = rp[dd];
                r = min(max(r, -POS_BND), POS_BND);
                s += stab[(r + POS_BND + dd * RPE_NUM) * HEADS + h];
            }
        }
        s += mask[((size_t)m * TOK + i) * TOK + j];
        sscore[(h * TOK + i) * TOK + j] = s;
    }
    __syncthreads();

    int lane = tid & 31, warp = tid >> 5;
    for (int r = warp; r < HEADS * TOK; r += 16) {
        float* rowp = sscore + r * TOK;
        float x0 = rowp[lane];
        float x1 = (lane == 0) ? rowp[32] : -1e30f;
        float mx = fmaxf(x0, x1);
        #pragma unroll
        for (int o = 16; o; o >>= 1) mx = fmaxf(mx, __shfl_xor_sync(0xffffffffu, mx, o));
        float e0 = __expf(x0 - mx);
        float e1 = (lane == 0) ? __expf(x1 - mx) : 0.f;
        float s = e0 + e1;
        #pragma unroll
        for (int o = 16; o; o >>= 1) s += __shfl_xor_sync(0xffffffffu, s, o);
        float inv = 1.f / s;
        rowp[lane] = e0 * inv;
        if (lane == 0) rowp[32] = e1 * inv;
    }
    __syncthreads();

    int h = (tid >> 5) & 7, d = lane, pair = tid >> 8;
    const __half* vb = sqh + 2 * CCH + h * HDIM + d;
    __half* ob = outbuf + ((size_t)m * TOK) * CCH + h * HDIM + d;
    for (int i = pair; i < TOK; i += 2) {
        const float* srow = sscore + (h * TOK + i) * TOK;
        float acc = 0.f;
        #pragma unroll
        for (int j = 0; j < TOK; j++) acc += srow[j] * __half2float(vb[(size_t)j * C3]);
        ob[(size_t)i * CCH] = __float2half(acc);
    }
}

// ---------------- host launcher ----------------
extern "C" void kernel_launch(void* const* d_in, const int* in_sizes, int n_in,
                              void* d_out, int out_size)
{
    const float* data      = (const float*)d_in[0];
    const float* rt        = (const float*)d_in[1];
    const int*   neighbors = (const int*)  d_in[2];
    const int*   rel_pos   = (const int*)  d_in[3];
    const float* mask      = (const float*)d_in[4];
    const float* cpe_w     = (const float*)d_in[5];
    const float* cpe_scale = (const float*)d_in[6];
    const float* cpe_bias  = (const float*)d_in[7];
    const float* ln1_g     = (const float*)d_in[8];
    const float* ln1_b     = (const float*)d_in[9];
    const float* qkv_w     = (const float*)d_in[10];
    const float* qkv_b     = (const float*)d_in[11];
    const float* rpe_table = (const float*)d_in[12];
    const float* proj_w    = (const float*)d_in[13];
    const float* proj_b    = (const float*)d_in[14];
    const float* ln2_g     = (const float*)d_in[15];
    const float* ln2_b     = (const float*)d_in[16];
    const float* mlp_w1    = (const float*)d_in[17];
    const float* mlp_b1    = (const float*)d_in[18];
    const float* mlp_w2    = (const float*)d_in[19];
    const float* mlp_b2    = (const float*)d_in[20];
    float* out = (float*)d_out;

    float*  xbuf;  cudaGetSymbolAddress((void**)&xbuf,  g_xbuf);
    __half* hbuf;  cudaGetSymbolAddress((void**)&hbuf,  g_hbuf16);
    __half* big;   cudaGetSymbolAddress((void**)&big,   g_big16);
    __half* wT;    cudaGetSymbolAddress((void**)&wT,    g_wT16);

    __half* qkvT  = wT;
    __half* projT = qkvT + 768 * 256;
    __half* mlp1T = projT + 256 * 256;
    __half* mlp2T = mlp1T + 1024 * 256;

    cudaFuncSetAttribute(attn_kernel, cudaFuncAttributeMaxDynamicSharedMemorySize, ATTN_SMEM);
    cudaFuncSetAttribute(hg256h<0>,       cudaFuncAttributeMaxDynamicSharedMemorySize, GEMM256H_SMEM);
    cudaFuncSetAttribute(hg128h<2>,       cudaFuncAttributeMaxDynamicSharedMemorySize, GEMMH_SMEM);
    cudaFuncSetAttribute(hg128<3, float>, cudaFuncAttributeMaxDynamicSharedMemorySize, GEMM1_SMEM);
    cudaFuncSetAttribute(hg256h_ln,       cudaFuncAttributeMaxDynamicSharedMemorySize, GEMM256H_SMEM);

    // 0. weight transposes + data fp16 mirror
    wt_all<<<dim3(32, 32, 4), 256>>>(qkv_w, proj_w, mlp_w1, mlp_w2,
                                     qkvT, projT, mlp1T, mlp2T);
    cvt_data_kernel<<<(NPTS * CCH) / (256 * 4), 256>>>(data);

    // 1. CPE + residual + LN1
    cpe_ln_kernel<<<NPTS + MWIN, 128>>>(data, rt, neighbors, cpe_w, cpe_scale,
                                        cpe_bias, ln1_g, ln1_b);

    // 2. QKV (fp16 acc, 128x256 tile — best shape for this GEMM)
    hg256h<0><<<dim3(C3/256, ROWS/128), 256, GEMM256H_SMEM>>>(
        hbuf, qkvT, qkv_b, big, CCH, C3);

    // 3. attention
    attn_kernel<<<MWIN, ATTN_THREADS, ATTN_SMEM>>>(big, rel_pos, mask, rpe_table, hbuf);

    // 4. proj + residual + fused LN2 (fp16 acc, 2 CTAs/SM)
    hg256h_ln<<<dim3(1, ROWS/128), 256, GEMM256H_SMEM>>>(
        hbuf, projT, proj_b, xbuf, xbuf, CCH, CCH, ln2_g, ln2_b, hbuf);

    // 5. hidden = gelu(h @ mlp_w1) (fp16 acc, 128x128 tile — best shape for this GEMM)
    hg128h<2><<<dim3(HID/128, ROWS/128), 256, GEMMH_SMEM>>>(
        hbuf, mlp1T, mlp_b1, big, CCH, HID);

    // 6. out = x + hidden @ mlp_w2 (fp32 acc, scattered)
    hg128<3, float><<<dim3(CCH/128, ROWS/128), 256, GEMM1_SMEM>>>(
        big, mlp2T, mlp_b2, out, xbuf, HID, CCH);
}

// round 17
// speedup vs baseline: 1.0158x; 1.0158x over previous
#include <cuda_runtime.h>
#include <cuda_fp16.h>
#include <math.h>
#include <stdint.h>

// ---------------- problem constants ----------------
#define MWIN   8192
#define KTOK   32
#define TOK    33          // K + G
#define CCH    256
#define HEADS  8
#define HDIM   32
#define NPTS   (MWIN * KTOK)        // 262144
#define ROWS   (MWIN * TOK)         // 270336
#define HID    1024
#define NEIGH  27
#define POS_BND 25
#define RPE_NUM 51
#define C3     768

// ---------------- scratch ----------------
__device__ float  g_xbuf [(size_t)ROWS * CCH];
__device__ __half g_hbuf16[(size_t)ROWS * CCH];
__device__ __half g_big16 [(size_t)ROWS * HID];
__device__ __half g_wT16  [768*256 + 256*256 + 1024*256 + 256*1024];
__device__ __half g_data16[(size_t)NPTS * CCH];

// ---------------- PTX helpers ----------------
__device__ __forceinline__ uint32_t smem_u32(const void* p) {
    uint32_t a;
    asm("{ .reg .u64 t; cvta.to.shared.u64 t, %1; cvt.u32.u64 %0, t; }" : "=r"(a) : "l"(p));
    return a;
}
#define CP_ASYNC16(dst_u32, src_ptr) \
    asm volatile("cp.async.cg.shared.global [%0], [%1], 16;\n" :: "r"(dst_u32), "l"(src_ptr))
#define CP_COMMIT() asm volatile("cp.async.commit_group;\n")
#define CP_WAIT(n)  asm volatile("cp.async.wait_group %0;\n" :: "n"(n))

#define LDSM_X4(r0,r1,r2,r3,a) \
    asm volatile("ldmatrix.sync.aligned.m8n8.x4.shared.b16 {%0,%1,%2,%3}, [%4];" \
        : "=r"(r0),"=r"(r1),"=r"(r2),"=r"(r3) : "r"(a))

#define HMMA16816(d, a, b) \
    asm volatile("mma.sync.aligned.m16n8k16.row.col.f32.f16.f16.f32 " \
        "{%0,%1,%2,%3},{%4,%5,%6,%7},{%8,%9},{%0,%1,%2,%3};" \
        : "+f"((d)[0]),"+f"((d)[1]),"+f"((d)[2]),"+f"((d)[3]) \
        : "r"((a)[0]),"r"((a)[1]),"r"((a)[2]),"r"((a)[3]),"r"((b)[0]),"r"((b)[1]))

#define HMMA16816H(d, a, b) \
    asm volatile("mma.sync.aligned.m16n8k16.row.col.f16.f16.f16.f16 " \
        "{%0,%1},{%2,%3,%4,%5},{%6,%7},{%0,%1};" \
        : "+r"((d)[0]), "+r"((d)[1]) \
        : "r"((a)[0]),"r"((a)[1]),"r"((a)[2]),"r"((a)[3]),"r"((b)[0]),"r"((b)[1]))

// ---------------- merged weight transpose ----------------
__global__ void __launch_bounds__(256) wt_all(
    const float* __restrict__ w0, const float* __restrict__ w1,
    const float* __restrict__ w2, const float* __restrict__ w3,
    __half* __restrict__ o0, __half* __restrict__ o1,
    __half* __restrict__ o2, __half* __restrict__ o3)
{
    int z = blockIdx.z;
    const float* in; __half* out; int K, N;
    if      (z == 0) { in = w0; out = o0; K = 256;  N = 768;  }
    else if (z == 1) { in = w1; out = o1; K = 256;  N = 256;  }
    else if (z == 2) { in = w2; out = o2; K = 256;  N = 1024; }
    else             { in = w3; out = o3; K = 1024; N = 256;  }
    int bx = blockIdx.x * 32, by = blockIdx.y * 32;
    if (bx >= N || by >= K) return;

    __shared__ float tile[32][33];
    int x = threadIdx.x & 31, y = threadIdx.x >> 5;
    #pragma unroll
    for (int i = 0; i < 32; i += 8)
        tile[y + i][x] = in[(size_t)(by + y + i) * N + bx + x];
    __syncthreads();
    #pragma unroll
    for (int i = 0; i < 32; i += 8)
        out[(size_t)(bx + y + i) * K + by + x] = __float2half(tile[x][y + i]);
}

// ---------------- data -> fp16 mirror ----------------
__global__ void __launch_bounds__(256) cvt_data_kernel(const float* __restrict__ data)
{
    size_t i = ((size_t)blockIdx.x * 256 + threadIdx.x) * 4;
    float4 f = *(const float4*)(data + i);
    __half2* d = (__half2*)(g_data16 + i);
    d[0] = __floats2half2_rn(f.x, f.y);
    d[1] = __floats2half2_rn(f.z, f.w);
}

// ---------------- CPE gather + residual + fused LN1 ----------------
__global__ void __launch_bounds__(128) cpe_ln_kernel(
    const float* __restrict__ data, const float* __restrict__ rt,
    const int* __restrict__ neighbors, const float* __restrict__ cpe_w,
    const float* __restrict__ cpe_scale, const float* __restrict__ cpe_bias,
    const float* __restrict__ gam, const float* __restrict__ bet)
{
    __shared__ int nb[NEIGH];
    __shared__ float red[8];
    int bid = blockIdx.x;
    int tid = threadIdx.x;
    int c = tid * 2;
    float2 v;
    size_t row;

    if (bid >= NPTS) {
        int m = bid - NPTS;
        row = (size_t)m * TOK;
        v = *(const float2*)(rt + (size_t)m * CCH + c);
    } else {
        if (tid < NEIGH) nb[tid] = neighbors[(size_t)bid * NEIGH + tid];
        __syncthreads();
        float ax = 0.f, ay = 0.f;
        #pragma unroll
        for (int j = 0; j < NEIGH; j++) {
            __half2 h = *(const __half2*)(g_data16 + (size_t)nb[j] * CCH + c);
            float2 f = __half22float2(h);
            float2 w = *(const float2*)(cpe_w + j * CCH + c);
            ax += f.x * w.x; ay += f.y * w.y;
        }
        float2 d0 = *(const float2*)(data + (size_t)bid * CCH + c);
        float2 sc = *(const float2*)(cpe_scale + c);
        float2 bi = *(const float2*)(cpe_bias + c);
        v = make_float2(d0.x + ax * sc.x + bi.x, d0.y + ay * sc.y + bi.y);
        int m = bid >> 5, k = bid & 31;
        row = (size_t)m * TOK + 1 + k;
    }
    *(float2*)(g_xbuf + row * CCH + c) = v;

    float s1 = v.x + v.y;
    float s2 = v.x * v.x + v.y * v.y;
    #pragma unroll
    for (int o = 16; o; o >>= 1) {
        s1 += __shfl_xor_sync(0xffffffffu, s1, o);
        s2 += __shfl_xor_sync(0xffffffffu, s2, o);
    }
    int warp = tid >> 5, lane = tid & 31;
    if (lane == 0) { red[warp] = s1; red[4 + warp] = s2; }
    __syncthreads();
    s1 = red[0] + red[1] + red[2] + red[3];
    s2 = red[4] + red[5] + red[6] + red[7];
    float mean = s1 * (1.f / 256.f);
    float var = s2 * (1.f / 256.f) - mean * mean;
    float rstd = rsqrtf(var + 1e-5f);
    float2 gm = *(const float2*)(gam + c);
    float2 bt = *(const float2*)(bet + c);
    *(__half2*)(g_hbuf16 + row * CCH + c) = __floats2half2_rn(
        (v.x - mean) * rstd * gm.x + bt.x, (v.y - mean) * rstd * gm.y + bt.y);
}

#define A_TILE1  10240            // 128 rows * 80 bytes
#define B_TILE1  20480            // 256 rows * 80 bytes

// ===== hg256h: fp16-acc GEMM, CTA 128x256, warp tile 64x64, 2 CTAs/SM (qkv) =====
#define GEMM256H_SMEM (3 * (A_TILE1 + B_TILE1))   // 92160

template<int MODE>
__global__ void __launch_bounds__(256, 2) hg256h(
    const __half* __restrict__ A, const __half* __restrict__ Bt,
    const float* __restrict__ bias, __half* __restrict__ Cout,
    int Kdim, int Ndim)
{
    extern __shared__ char smraw[];
    uint32_t base = smem_u32(smraw);

    int tid = threadIdx.x;
    int warp = tid >> 5, lane = tid & 31;
    int wm = (warp >> 2) * 64;
    int wn = (warp & 3) * 64;
    int la = lane & 7, grp = lane >> 3;
    int g = lane >> 2, t = lane & 3;

    size_t rowBase = (size_t)blockIdx.y * 128;
    int colBase = blockIdx.x * 256;

    const __half* Ag = A  + rowBase * Kdim;
    const __half* Bg = Bt + (size_t)colBase * Kdim;

    int aRow = la + (grp & 1) * 8;
    int aKof = (grp >> 1) * 8;
    int bRow = la + (grp >> 1) * 8;
    int bKof = (grp & 1) * 8;

    uint32_t accH[4][8][2];
    #pragma unroll
    for (int mt = 0; mt < 4; mt++)
        #pragma unroll
        for (int nt = 0; nt < 8; nt++) { accH[mt][nt][0] = 0u; accH[mt][nt][1] = 0u; }

    auto loadStage = [&](int s, int k0) {
        #pragma unroll
        for (int i = 0; i < 2; i++) {
            int idx = i * 256 + tid;
            int row = idx >> 2, c = idx & 3;
            CP_ASYNC16(base + s * A_TILE1 + row * 80 + c * 16,
                       Ag + (size_t)row * Kdim + k0 + c * 8);
        }
        #pragma unroll
        for (int i = 0; i < 4; i++) {
            int idx = i * 256 + tid;
            int row = idx >> 2, c = idx & 3;
            CP_ASYNC16(base + 3 * A_TILE1 + s * B_TILE1 + row * 80 + c * 16,
                       Bg + (size_t)row * Kdim + k0 + c * 8);
        }
    };

    int KT = Kdim >> 5;
    loadStage(0, 0);  CP_COMMIT();
    loadStage(1, 32); CP_COMMIT();

    for (int kt = 0; kt < KT; kt++) {
        if (kt + 1 < KT) CP_WAIT(1); else CP_WAIT(0);
        __syncthreads();
        if (kt + 2 < KT) { loadStage((kt + 2) % 3, (kt + 2) << 5); CP_COMMIT(); }

        int buf = kt % 3;
        uint32_t aBase = base + buf * A_TILE1;
        uint32_t bBase = base + 3 * A_TILE1 + buf * B_TILE1;

        #pragma unroll
        for (int kk = 0; kk < 2; kk++) {
            int kb = kk * 16;
            uint32_t af[4][4], bf[8][2];
            #pragma unroll
            for (int mt = 0; mt < 4; mt++) {
                uint32_t ad = aBase + (uint32_t)(wm + mt * 16 + aRow) * 80
                            + (uint32_t)(kb + aKof) * 2;
                LDSM_X4(af[mt][0], af[mt][1], af[mt][2], af[mt][3], ad);
            }
            #pragma unroll
            for (int np = 0; np < 4; np++) {
                uint32_t bd = bBase + (uint32_t)(wn + np * 16 + bRow) * 80
                            + (uint32_t)(kb + bKof) * 2;
                LDSM_X4(bf[2*np][0], bf[2*np][1], bf[2*np+1][0], bf[2*np+1][1], bd);
            }
            #pragma unroll
            for (int mt = 0; mt < 4; mt++)
                #pragma unroll
                for (int nt = 0; nt < 8; nt++)
                    HMMA16816H(accH[mt][nt], af[mt], bf[nt]);
        }
    }

    #pragma unroll
    for (int mt = 0; mt < 4; mt++) {
        #pragma unroll
        for (int nt = 0; nt < 8; nt++) {
            int col = colBase + wn + nt * 8 + 2 * t;
            float b0 = bias[col], b1 = bias[col + 1];
            #pragma unroll
            for (int hf = 0; hf < 2; hf++) {
                size_t row = rowBase + wm + mt * 16 + g + hf * 8;
                float2 f = __half22float2(*(__half2*)&accH[mt][nt][hf]);
                float v0 = f.x + b0;
                float v1 = f.y + b1;
                if (MODE == 2) {
                    v0 = 0.5f * v0 * (1.0f + erff(v0 * 0.70710678118654752f));
                    v1 = 0.5f * v1 * (1.0f + erff(v1 * 0.70710678118654752f));
                }
                *(__half2*)&Cout[row * Ndim + col] = __floats2half2_rn(v0, v1);
            }
        }
    }
}

// ===== hg128h: fp16-acc GEMM, CTA 128x128, 3 CTAs/SM (mlp1) =====
#define GEMMH_SMEM (6 * A_TILE1)  // 61440

template<int MODE>
__global__ void __launch_bounds__(256, 3) hg128h(
    const __half* __restrict__ A, const __half* __restrict__ Bt,
    const float* __restrict__ bias, __half* __restrict__ Cout,
    int Kdim, int Ndim)
{
    extern __shared__ char smraw[];
    uint32_t base = smem_u32(smraw);

    int tid = threadIdx.x;
    int warp = tid >> 5, lane = tid & 31;
    int wm = (warp >> 2) * 64;
    int wn = (warp & 3) * 32;
    int la = lane & 7, grp = lane >> 3;
    int g = lane >> 2, t = lane & 3;

    size_t rowBase = (size_t)blockIdx.y * 128;
    int colBase = blockIdx.x * 128;

    const __half* Ag = A  + rowBase * Kdim;
    const __half* Bg = Bt + (size_t)colBase * Kdim;

    int aRow = la + (grp & 1) * 8;
    int aKof = (grp >> 1) * 8;
    int bRow = la + (grp >> 1) * 8;
    int bKof = (grp & 1) * 8;

    uint32_t accH[4][4][2];
    #pragma unroll
    for (int mt = 0; mt < 4; mt++)
        #pragma unroll
        for (int nt = 0; nt < 4; nt++) { accH[mt][nt][0] = 0u; accH[mt][nt][1] = 0u; }

    auto loadStage = [&](int s, int k0) {
        #pragma unroll
        for (int i = 0; i < 2; i++) {
            int idx = i * 256 + tid;
            int row = idx >> 2, c = idx & 3;
            CP_ASYNC16(base + s * A_TILE1 + row * 80 + c * 16,
                       Ag + (size_t)row * Kdim + k0 + c * 8);
            CP_ASYNC16(base + (3 + s) * A_TILE1 + row * 80 + c * 16,
                       Bg + (size_t)row * Kdim + k0 + c * 8);
        }
    };

    int KT = Kdim >> 5;
    loadStage(0, 0);  CP_COMMIT();
    loadStage(1, 32); CP_COMMIT();

    for (int kt = 0; kt < KT; kt++) {
        if (kt + 1 < KT) CP_WAIT(1); else CP_WAIT(0);
        __syncthreads();
        if (kt + 2 < KT) { loadStage((kt + 2) % 3, (kt + 2) << 5); CP_COMMIT(); }

        int buf = kt % 3;
        uint32_t aBase = base + buf * A_TILE1;
        uint32_t bBase = base + (3 + buf) * A_TILE1;

        #pragma unroll
        for (int kk = 0; kk < 2; kk++) {
            int kb = kk * 16;
            uint32_t af[4][4], bf[4][2];
            #pragma unroll
            for (int mt = 0; mt < 4; mt++) {
                uint32_t ad = aBase + (uint32_t)(wm + mt * 16 + aRow) * 80
                            + (uint32_t)(kb + aKof) * 2;
                LDSM_X4(af[mt][0], af[mt][1], af[mt][2], af[mt][3], ad);
            }
            #pragma unroll
            for (int np = 0; np < 2; np++) {
                uint32_t bd = bBase + (uint32_t)(wn + np * 16 + bRow) * 80
                            + (uint32_t)(kb + bKof) * 2;
                LDSM_X4(bf[2*np][0], bf[2*np][1], bf[2*np+1][0], bf[2*np+1][1], bd);
            }
            #pragma unroll
            for (int mt = 0; mt < 4; mt++)
                #pragma unroll
                for (int nt = 0; nt < 4; nt++)
                    HMMA16816H(accH[mt][nt], af[mt], bf[nt]);
        }
        __syncthreads();
    }

    #pragma unroll
    for (int mt = 0; mt < 4; mt++) {
        #pragma unroll
        for (int nt = 0; nt < 4; nt++) {
            int col = colBase + wn + nt * 8 + 2 * t;
            float b0 = bias[col], b1 = bias[col + 1];
            #pragma unroll
            for (int hf = 0; hf < 2; hf++) {
                size_t row = rowBase + wm + mt * 16 + g + hf * 8;
                float2 f = __half22float2(*(__half2*)&accH[mt][nt][hf]);
                float v0 = f.x + b0;
                float v1 = f.y + b1;
                if (MODE == 2) {
                    v0 = 0.5f * v0 * (1.0f + erff(v0 * 0.70710678118654752f));
                    v1 = 0.5f * v1 * (1.0f + erff(v1 * 0.70710678118654752f));
                }
                *(__half2*)&Cout[row * Ndim + col] = __floats2half2_rn(v0, v1);
            }
        }
    }
}

// ===== hg128: fp32-acc GEMM (mlp2/output), CTA 128x128, 2 CTAs/SM, 5-stage =====
#define NSTG     5
#define GEMM1_SMEM (2 * NSTG * A_TILE1)  // 102400

template<int MODE, typename OutT>
__global__ void __launch_bounds__(256, 2) hg128(
    const __half* __restrict__ A, const __half* __restrict__ Bt,
    const float* __restrict__ bias, OutT* __restrict__ Cout,
    const float* __restrict__ res, int Kdim, int Ndim)
{
    extern __shared__ char smraw[];
    uint32_t base = smem_u32(smraw);

    int tid = threadIdx.x;
    int warp = tid >> 5, lane = tid & 31;
    int wm = (warp >> 2) * 64;
    int wn = (warp & 3) * 32;
    int la = lane & 7, grp = lane >> 3;
    int g = lane >> 2, t = lane & 3;

    size_t rowBase = (size_t)blockIdx.y * 128;
    int colBase = blockIdx.x * 128;

    const __half* Ag = A  + rowBase * Kdim;
    const __half* Bg = Bt + (size_t)colBase * Kdim;

    int aRow = la + (grp & 1) * 8;
    int aKof = (grp >> 1) * 8;
    int bRow = la + (grp >> 1) * 8;
    int bKof = (grp & 1) * 8;

    float acc[4][4][4];
    #pragma unroll
    for (int mt = 0; mt < 4; mt++)
        #pragma unroll
        for (int nt = 0; nt < 4; nt++)
            #pragma unroll
            for (int i = 0; i < 4; i++) acc[mt][nt][i] = 0.f;

    auto loadStage = [&](int s, int k0) {
        #pragma unroll
        for (int i = 0; i < 2; i++) {
            int idx = i * 256 + tid;
            int row = idx >> 2, c = idx & 3;
            CP_ASYNC16(base + s * A_TILE1 + row * 80 + c * 16,
                       Ag + (size_t)row * Kdim + k0 + c * 8);
            CP_ASYNC16(base + (NSTG + s) * A_TILE1 + row * 80 + c * 16,
                       Bg + (size_t)row * Kdim + k0 + c * 8);
        }
    };

    auto computeStage = [&](int buf) {
        uint32_t aBase = base + buf * A_TILE1;
        uint32_t bBase = base + (NSTG + buf) * A_TILE1;
        #pragma unroll
        for (int kk = 0; kk < 2; kk++) {
            int kb = kk * 16;
            uint32_t af[4][4], bf[4][2];
            #pragma unroll
            for (int mt = 0; mt < 4; mt++) {
                uint32_t ad = aBase + (uint32_t)(wm + mt * 16 + aRow) * 80
                            + (uint32_t)(kb + aKof) * 2;
                LDSM_X4(af[mt][0], af[mt][1], af[mt][2], af[mt][3], ad);
            }
            #pragma unroll
            for (int np = 0; np < 2; np++) {
                uint32_t bd = bBase + (uint32_t)(wn + np * 16 + bRow) * 80
                            + (uint32_t)(kb + bKof) * 2;
                LDSM_X4(bf[2*np][0], bf[2*np][1], bf[2*np+1][0], bf[2*np+1][1], bd);
            }
            #pragma unroll
            for (int mt = 0; mt < 4; mt++)
                #pragma unroll
                for (int nt = 0; nt < 4; nt++)
                    HMMA16816(acc[mt][nt], af[mt], bf[nt]);
        }
    };

    int KT = Kdim >> 5;
    loadStage(0, 0);   CP_COMMIT();
    loadStage(1, 32);  CP_COMMIT();
    loadStage(2, 64);  CP_COMMIT();

    for (int kt = 0; kt < KT; kt += 2) {
        if (kt + 2 < KT) CP_WAIT(1); else CP_WAIT(0);
        __syncthreads();
        if (kt + 3 < KT) { loadStage((kt + 3) % NSTG, (kt + 3) << 5); CP_COMMIT(); }
        if (kt + 4 < KT) { loadStage((kt + 4) % NSTG, (kt + 4) << 5); CP_COMMIT(); }
        computeStage(kt % NSTG);
        computeStage((kt + 1) % NSTG);
    }

    #pragma unroll
    for (int mt = 0; mt < 4; mt++) {
        #pragma unroll
        for (int nt = 0; nt < 4; nt++) {
            int col = colBase + wn + nt * 8 + 2 * t;
            float b0 = bias[col], b1 = bias[col + 1];
            #pragma unroll
            for (int hf = 0; hf < 2; hf++) {
                size_t row = rowBase + wm + mt * 16 + g + hf * 8;
                float v0 = acc[mt][nt][hf * 2 + 0] + b0;
                float v1 = acc[mt][nt][hf * 2 + 1] + b1;
                const float2 r2 = *(const float2*)&res[row * CCH + col];
                size_t m = row / TOK;
                int tt = (int)(row - m * TOK);
                float* dst = (tt == 0)
                    ? ((float*)Cout + (size_t)NPTS * CCH + m * CCH + col)
                    : ((float*)Cout + (m * KTOK + (size_t)(tt - 1)) * CCH + col);
                *(float2*)dst = make_float2(v0 + r2.x, v1 + r2.y);
            }
        }
    }
}

// ============ hgemm256_ln: proj + residual + fused LN2; 512 threads, fp32 acc ============
#define A_TILE   10240
#define B_TILE   20480
#define GEMM_SMEM (3 * (A_TILE + B_TILE))   // 92160

__global__ void __launch_bounds__(512, 1) hgemm256_ln(
    const __half* __restrict__ A, const __half* __restrict__ Bt,
    const float* __restrict__ bias, float* __restrict__ Cout,
    const float* __restrict__ res, int Kdim, int Ndim,
    const float* __restrict__ gam, const float* __restrict__ bet,
    __half* __restrict__ hout)
{
    extern __shared__ char smraw[];
    uint32_t base = smem_u32(smraw);
    float* lnsum = (float*)smraw;
    float* lnsq  = (float*)smraw + 128;

    int tid = threadIdx.x;
    int warp = tid >> 5, lane = tid & 31;
    int wm = (warp >> 3) * 64;
    int wn = (warp & 7) * 32;
    int la = lane & 7, grp = lane >> 3;
    int g = lane >> 2, t = lane & 3;

    size_t rowBase = (size_t)blockIdx.y * 128;

    const __half* Ag = A + rowBase * Kdim;
    const __half* Bg = Bt;

    int aRow = la + (grp & 1) * 8;
    int aKof = (grp >> 1) * 8;
    int bRow = la + (grp >> 1) * 8;
    int bKof = (grp & 1) * 8;

    float acc[4][4][4];
    #pragma unroll
    for (int mt = 0; mt < 4; mt++)
        #pragma unroll
        for (int nt = 0; nt < 4; nt++)
            #pragma unroll
            for (int i = 0; i < 4; i++) acc[mt][nt][i] = 0.f;

    auto loadStage = [&](int s, int k0) {
        {
            int row = tid >> 2, c = tid & 3;
            CP_ASYNC16(base + s * A_TILE + row * 80 + c * 16,
                       Ag + (size_t)row * Kdim + k0 + c * 8);
        }
        #pragma unroll
        for (int i = 0; i < 2; i++) {
            int idx = i * 512 + tid;
            int row = idx >> 2, c = idx & 3;
            CP_ASYNC16(base + 3 * A_TILE + s * B_TILE + row * 80 + c * 16,
                       Bg + (size_t)row * Kdim + k0 + c * 8);
        }
    };

    int KT = Kdim >> 5;
    loadStage(0, 0);  CP_COMMIT();
    loadStage(1, 32); CP_COMMIT();

    for (int kt = 0; kt < KT; kt++) {
        if (kt + 1 < KT) CP_WAIT(1); else CP_WAIT(0);
        __syncthreads();
        if (kt + 2 < KT) { loadStage((kt + 2) % 3, (kt + 2) << 5); CP_COMMIT(); }

        int buf = kt % 3;
        uint32_t aBase = base + buf * A_TILE;
        uint32_t bBase = base + 3 * A_TILE + buf * B_TILE;

        #pragma unroll
        for (int kk = 0; kk < 2; kk++) {
            int kb = kk * 16;
            uint32_t af[4][4], bf[4][2];
            #pragma unroll
            for (int mt = 0; mt < 4; mt++) {
                uint32_t ad = aBase + (uint32_t)(wm + mt * 16 + aRow) * 80
                            + (uint32_t)(kb + aKof) * 2;
                LDSM_X4(af[mt][0], af[mt][1], af[mt][2], af[mt][3], ad);
            }
            #pragma unroll
            for (int np = 0; np < 2; np++) {
                uint32_t bd = bBase + (uint32_t)(wn + np * 16 + bRow) * 80
                            + (uint32_t)(kb + bKof) * 2;
                LDSM_X4(bf[2*np][0], bf[2*np][1], bf[2*np+1][0], bf[2*np+1][1], bd);
            }
            #pragma unroll
            for (int mt = 0; mt < 4; mt++)
                #pragma unroll
                for (int nt = 0; nt < 4; nt++)
                    HMMA16816(acc[mt][nt], af[mt], bf[nt]);
        }
    }

    __syncthreads();
    if (tid < 128) lnsum[tid] = 0.f;
    else if (tid < 256) lnsq[tid - 128] = 0.f;
    __syncthreads();

    #pragma unroll
    for (int mt = 0; mt < 4; mt++) {
        #pragma unroll
        for (int nt = 0; nt < 4; nt++) {
            int col = wn + nt * 8 + 2 * t;
            float b0 = bias[col], b1 = bias[col + 1];
            #pragma unroll
            for (int hf = 0; hf < 2; hf++) {
                size_t row = rowBase + wm + mt * 16 + g + hf * 8;
                const float2 r2 = *(const float2*)&res[row * Ndim + col];
                float v0 = acc[mt][nt][hf * 2 + 0] + b0 + r2.x;
                float v1 = acc[mt][nt][hf * 2 + 1] + b1 + r2.y;
                acc[mt][nt][hf * 2 + 0] = v0;
                acc[mt][nt][hf * 2 + 1] = v1;
                *(float2*)&Cout[row * Ndim + col] = make_float2(v0, v1);
            }
        }
    }

    #pragma unroll
    for (int mt = 0; mt < 4; mt++) {
        #pragma unroll
        for (int hf = 0; hf < 2; hf++) {
            int rloc = wm + mt * 16 + g + hf * 8;
            float s1 = 0.f, s2 = 0.f;
            #pragma unroll
            for (int nt = 0; nt < 4; nt++) {
                float v0 = acc[mt][nt][hf * 2 + 0];
                float v1 = acc[mt][nt][hf * 2 + 1];
                s1 += v0 + v1;
                s2 += v0 * v0 + v1 * v1;
            }
            s1 += __shfl_xor_sync(0xffffffffu, s1, 1);
            s1 += __shfl_xor_sync(0xffffffffu, s1, 2);
            s2 += __shfl_xor_sync(0xffffffffu, s2, 1);
            s2 += __shfl_xor_sync(0xffffffffu, s2, 2);
            if (t == 0) {
                atomicAdd(&lnsum[rloc], s1);
                atomicAdd(&lnsq[rloc],  s2);
            }
        }
    }
    __syncthreads();
    #pragma unroll
    for (int mt = 0; mt < 4; mt++) {
        #pragma unroll
        for (int hf = 0; hf < 2; hf++) {
            int rloc = wm + mt * 16 + g + hf * 8;
            size_t row = rowBase + rloc;
            float mean = lnsum[rloc] * (1.f / 256.f);
            float var  = lnsq[rloc] * (1.f / 256.f) - mean * mean;
            float rstd = rsqrtf(var + 1e-5f);
            #pragma unroll
            for (int nt = 0; nt < 4; nt++) {
                int col = wn + nt * 8 + 2 * t;
                float v0 = acc[mt][nt][hf * 2 + 0];
                float v1 = acc[mt][nt][hf * 2 + 1];
                float o0 = (v0 - mean) * rstd * gam[col]     + bet[col];
                float o1 = (v1 - mean) * rstd * gam[col + 1] + bet[col + 1];
                *(__half2*)&hout[row * CCH + col] = __floats2half2_rn(o0, o1);
            }
        }
    }
}

// ---------------- fused per-window attention (R7 exact) ----------------
#define ATTN_THREADS 512
#define SQH_H  (TOK * C3)
#define KT2_E  ((CCH / 2) * TOK)
#define SC_F   (HEADS * TOK * TOK)
#define TAB_F  (3 * RPE_NUM * HEADS)
#define ATTN_SMEM (SQH_H * 2 + KT2_E * 4 + SC_F * 4 + TAB_F * 4)

__global__ void __launch_bounds__(ATTN_THREADS) attn_kernel(
    const __half* __restrict__ qkv, const int* __restrict__ rel_pos,
    const float* __restrict__ mask, const float* __restrict__ rpe_table,
    __half* __restrict__ outbuf)
{
    extern __shared__ char smc[];
    __half*  sqh    = (__half*)smc;
    __half2* ktb2   = (__half2*)(smc + SQH_H * 2);
    float*   sscore = (float*)(smc + SQH_H * 2 + KT2_E * 4);
    float*   stab   = sscore + SC_F;

    int m = blockIdx.x, tid = threadIdx.x;
    const __half2* src = (const __half2*)(qkv + (size_t)m * TOK * C3);
    __half2* dsq = (__half2*)sqh;
    for (int i = tid; i < SQH_H / 2; i += ATTN_THREADS) dsq[i] = src[i];
    for (int i = tid; i < TAB_F; i += ATTN_THREADS) stab[i] = rpe_table[i];
    __syncthreads();

    for (int idx = tid; idx < KT2_E; idx += ATTN_THREADS) {
        int c2 = idx & 127, j = idx >> 7;
        ktb2[c2 * TOK + j] = *(const __half2*)(sqh + j * C3 + CCH + c2 * 2);
    }
    __syncthreads();

    const float scale = 0.17677669529663687f;

    for (int idx = tid; idx < SC_F; idx += ATTN_THREADS) {
        int j = idx % TOK;
        int ih = idx / TOK;
        int i = ih % TOK;
        int h = ih / TOK;
        const __half2* qp = (const __half2*)(sqh + i * C3 + h * HDIM);
        const __half2* kp = ktb2 + (h * 16) * TOK + j;
        float s = 0.f;
        #pragma unroll
        for (int d2 = 0; d2 < 16; d2++) {
            float2 q2 = __half22float2(qp[d2]);
            float2 k2 = __half22float2(kp[d2 * TOK]);
            s += q2.x * k2.x + q2.y * k2.y;
        }
        s *= scale;
        if (i > 0 && j > 0) {
            const int* rp = rel_pos + (((size_t)m * KTOK + (i - 1)) * KTOK + (j - 1)) * 3;
            #pragma unroll
            for (int dd = 0; dd < 3; dd++) {
                int r = rp[dd];
                r = min(max(r, -POS_BND), POS_BND);
                s += stab[(r + POS_BND + dd * RPE_NUM) * HEADS + h];
            }
        }
        s += mask[((size_t)m * TOK + i) * TOK + j];
        sscore[(h * TOK + i) * TOK + j] = s;
    }
    __syncthreads();

    int lane = tid & 31, warp = tid >> 5;
    for (int r = warp; r < HEADS * TOK; r += 16) {
        float* rowp = sscore + r * TOK;
        float x0 = rowp[lane];
        float x1 = (lane == 0) ? rowp[32] : -1e30f;
        float mx = fmaxf(x0, x1);
        #pragma unroll
        for (int o = 16; o; o >>= 1) mx = fmaxf(mx, __shfl_xor_sync(0xffffffffu, mx, o));
        float e0 = __expf(x0 - mx);
        float e1 = (lane == 0) ? __expf(x1 - mx) : 0.f;
        float s = e0 + e1;
        #pragma unroll
        for (int o = 16; o; o >>= 1) s += __shfl_xor_sync(0xffffffffu, s, o);
        float inv = 1.f / s;
        rowp[lane] = e0 * inv;
        if (lane == 0) rowp[32] = e1 * inv;
    }
    __syncthreads();

    int h = (tid >> 5) & 7, d = lane, pair = tid >> 8;
    const __half* vb = sqh + 2 * CCH + h * HDIM + d;
    __half* ob = outbuf + ((size_t)m * TOK) * CCH + h * HDIM + d;
    for (int i = pair; i < TOK; i += 2) {
        const float* srow = sscore + (h * TOK + i) * TOK;
        float acc = 0.f;
        #pragma unroll
        for (int j = 0; j < TOK; j++) acc += srow[j] * __half2float(vb[(size_t)j * C3]);
        ob[(size_t)i * CCH] = __float2half(acc);
    }
}

// ---------------- host launcher ----------------
extern "C" void kernel_launch(void* const* d_in, const int* in_sizes, int n_in,
                              void* d_out, int out_size)
{
    const float* data      = (const float*)d_in[0];
    const float* rt        = (const float*)d_in[1];
    const int*   neighbors = (const int*)  d_in[2];
    const int*   rel_pos   = (const int*)  d_in[3];
    const float* mask      = (const float*)d_in[4];
    const float* cpe_w     = (const float*)d_in[5];
    const float* cpe_scale = (const float*)d_in[6];
    const float* cpe_bias  = (const float*)d_in[7];
    const float* ln1_g     = (const float*)d_in[8];
    const float* ln1_b     = (const float*)d_in[9];
    const float* qkv_w     = (const float*)d_in[10];
    const float* qkv_b     = (const float*)d_in[11];
    const float* rpe_table = (const float*)d_in[12];
    const float* proj_w    = (const float*)d_in[13];
    const float* proj_b    = (const float*)d_in[14];
    const float* ln2_g     = (const float*)d_in[15];
    const float* ln2_b     = (const float*)d_in[16];
    const float* mlp_w1    = (const float*)d_in[17];
    const float* mlp_b1    = (const float*)d_in[18];
    const float* mlp_w2    = (const float*)d_in[19];
    const float* mlp_b2    = (const float*)d_in[20];
    float* out = (float*)d_out;

    float*  xbuf;  cudaGetSymbolAddress((void**)&xbuf,  g_xbuf);
    __half* hbuf;  cudaGetSymbolAddress((void**)&hbuf,  g_hbuf16);
    __half* big;   cudaGetSymbolAddress((void**)&big,   g_big16);
    __half* wT;    cudaGetSymbolAddress((void**)&wT,    g_wT16);

    __half* qkvT  = wT;
    __half* projT = qkvT + 768 * 256;
    __half* mlp1T = projT + 256 * 256;
    __half* mlp2T = mlp1T + 1024 * 256;

    cudaFuncSetAttribute(attn_kernel, cudaFuncAttributeMaxDynamicSharedMemorySize, ATTN_SMEM);
    cudaFuncSetAttribute(hg256h<0>,       cudaFuncAttributeMaxDynamicSharedMemorySize, GEMM256H_SMEM);
    cudaFuncSetAttribute(hg128h<2>,       cudaFuncAttributeMaxDynamicSharedMemorySize, GEMMH_SMEM);
    cudaFuncSetAttribute(hg128<3, float>, cudaFuncAttributeMaxDynamicSharedMemorySize, GEMM1_SMEM);
    cudaFuncSetAttribute(hgemm256_ln,     cudaFuncAttributeMaxDynamicSharedMemorySize, GEMM_SMEM);

    // 0. weight transposes + data fp16 mirror
    wt_all<<<dim3(32, 32, 4), 256>>>(qkv_w, proj_w, mlp_w1, mlp_w2,
                                     qkvT, projT, mlp1T, mlp2T);
    cvt_data_kernel<<<(NPTS * CCH) / (256 * 4), 256>>>(data);

    // 1. CPE + residual + LN1
    cpe_ln_kernel<<<NPTS + MWIN, 128>>>(data, rt, neighbors, cpe_w, cpe_scale,
                                        cpe_bias, ln1_g, ln1_b);

    // 2. QKV (fp16 acc, 128x256 tile — best shape)
    hg256h<0><<<dim3(C3/256, ROWS/128), 256, GEMM256H_SMEM>>>(
        hbuf, qkvT, qkv_b, big, CCH, C3);

    // 3. attention
    attn_kernel<<<MWIN, ATTN_THREADS, ATTN_SMEM>>>(big, rel_pos, mask, rpe_table, hbuf);

    // 4. proj + residual + fused LN2 (512 threads, fp32 acc — best known)
    hgemm256_ln<<<dim3(1, ROWS/128), 512, GEMM_SMEM>>>(
        hbuf, projT, proj_b, xbuf, xbuf, CCH, CCH, ln2_g, ln2_b, hbuf);

    // 5. hidden = gelu(h @ mlp_w1) (fp16 acc, 128x128 tile, 3 CTAs/SM — best shape)
    hg128h<2><<<dim3(HID/128, ROWS/128), 256, GEMMH_SMEM>>>(
        hbuf, mlp1T, mlp_b1, big, CCH, HID);

    // 6. out = x + hidden @ mlp_w2 (fp32 acc, scattered)
    hg128<3, float><<<dim3(CCH/128, ROWS/128), 256, GEMM1_SMEM>>>(
        big, mlp2T, mlp_b2, out, xbuf, HID, CCH);
}